// round 1
// baseline (speedup 1.0000x reference)
#include <cuda_runtime.h>
#include <math.h>

// ---------------------------------------------------------------------------
// Problem constants
//   B=2048, S=8 -> N = 16384 tokens, D = 1024, E = 8 experts, K(top)=2,
//   F = 1024, H=4, DQ=DKV=32, L=256, R=16, O=1024
// ---------------------------------------------------------------------------
#define NTOK   16384
#define DIM    1024
#define FDIM   1024
#define NEXP   8
#define NRB    264               // row-blocks for the flat (token,expert) list
#define MAXROWS (NRB * 128)      // 33792 >= 2*N + 8*127 padding

// ---------------------------------------------------------------------------
// Device scratch (static __device__ arrays: no allocation at runtime)
// ---------------------------------------------------------------------------
__device__ float g_hs  [(size_t)NTOK   * FDIM];  // shared-branch hidden
__device__ float g_h   [(size_t)MAXROWS * FDIM]; // expert hidden (flat rows)
__device__ float g_EO  [(size_t)NTOK   * DIM];   // expert_out (shared + experts)
__device__ float g_comb[(size_t)NTOK   * DIM];   // expert_out + attn_out
__device__ float g_q   [(size_t)NTOK * 128];
__device__ float g_lat [(size_t)NTOK * 256];
__device__ float g_k   [(size_t)NTOK * 128];
__device__ float g_v   [(size_t)NTOK * 128];
__device__ float g_attn[(size_t)NTOK * 128];

__device__ int   g_eidx[NTOK * 2];
__device__ float g_ew  [NTOK * 2];
__device__ int   g_counts[NEXP];
__device__ int   g_cursor[NEXP];
__device__ int   g_rbexp[NRB];      // expert id per 128-row block (-1 = unused)
__device__ int   g_ftok [MAXROWS];  // flat row -> token (-1 = padding)
__device__ float g_fw   [MAXROWS];  // flat row -> combine weight

// ---------------------------------------------------------------------------
// Helpers
// ---------------------------------------------------------------------------
__device__ __forceinline__ float gelu_f(float x) {
    return 0.5f * x * (1.0f + erff(x * 0.70710678118654752f));
}

// ---------------------------------------------------------------------------
// K0: zero per-expert counters
// ---------------------------------------------------------------------------
__global__ void zero_k(int* counts) {
    if (threadIdx.x < NEXP) counts[threadIdx.x] = 0;
}

// ---------------------------------------------------------------------------
// K1: routing — scores = sigmoid(x @ Wg) * route_scale ; top-2 ; normalize
// one thread per token; Wg (1024 x 8) staged in smem
// ---------------------------------------------------------------------------
__global__ void routing_k(const float* __restrict__ x,
                          const float* __restrict__ Wg,
                          const float* __restrict__ rsc,
                          int* __restrict__ eidx, float* __restrict__ ew,
                          int* __restrict__ counts) {
    __shared__ float sW[DIM * NEXP];  // 32 KB
    for (int i = threadIdx.x; i < DIM * NEXP; i += blockDim.x) sW[i] = Wg[i];
    __syncthreads();

    int t = blockIdx.x * blockDim.x + threadIdx.x;  // token
    float acc[NEXP];
#pragma unroll
    for (int e = 0; e < NEXP; e++) acc[e] = 0.f;

    const float* xr = x + (size_t)t * DIM;
    for (int k = 0; k < DIM; k += 4) {
        float4 xv = *(const float4*)(xr + k);
        const float* w0 = &sW[(k + 0) * NEXP];
        const float* w1 = &sW[(k + 1) * NEXP];
        const float* w2 = &sW[(k + 2) * NEXP];
        const float* w3 = &sW[(k + 3) * NEXP];
#pragma unroll
        for (int e = 0; e < NEXP; e++)
            acc[e] += xv.x * w0[e] + xv.y * w1[e] + xv.z * w2[e] + xv.w * w3[e];
    }
    float rs = rsc[0];
#pragma unroll
    for (int e = 0; e < NEXP; e++) acc[e] = rs / (1.f + expf(-acc[e]));

    // top-2 (lowest index wins on ties, matching jax top_k)
    int b0 = 0; float s0 = acc[0];
#pragma unroll
    for (int e = 1; e < NEXP; e++) if (acc[e] > s0) { s0 = acc[e]; b0 = e; }
    int b1 = -1; float s1 = -1e30f;
#pragma unroll
    for (int e = 0; e < NEXP; e++)
        if (e != b0 && acc[e] > s1) { s1 = acc[e]; b1 = e; }

    float inv = 1.f / (s0 + s1);
    eidx[t * 2 + 0] = b0; eidx[t * 2 + 1] = b1;
    ew[t * 2 + 0] = s0 * inv; ew[t * 2 + 1] = s1 * inv;
    atomicAdd(&counts[b0], 1);
    atomicAdd(&counts[b1], 1);
}

// ---------------------------------------------------------------------------
// K2: build 128-aligned per-expert segments, rowblock->expert map, cursors
// ---------------------------------------------------------------------------
__global__ void setup_k(const int* __restrict__ counts,
                        int* __restrict__ cursor,
                        int* __restrict__ rbexp,
                        int* __restrict__ ftok) {
    __shared__ int so[NEXP + 1];
    if (threadIdx.x == 0) {
        int o = 0;
        for (int e = 0; e < NEXP; e++) {
            so[e] = o;
            o += ((counts[e] + 127) >> 7) << 7;
        }
        so[NEXP] = o;
    }
    __syncthreads();
    if (threadIdx.x < NEXP) cursor[threadIdx.x] = so[threadIdx.x];
    for (int rb = threadIdx.x; rb < NRB; rb += blockDim.x) {
        int r = rb * 128, e = -1;
        for (int j = 0; j < NEXP; j++)
            if (r >= so[j] && r < so[j + 1]) e = j;
        rbexp[rb] = e;
    }
    for (int i = threadIdx.x; i < MAXROWS; i += blockDim.x) ftok[i] = -1;
}

// ---------------------------------------------------------------------------
// K3: scatter tokens into per-expert segments
// ---------------------------------------------------------------------------
__global__ void scatter_k(const int* __restrict__ eidx,
                          const float* __restrict__ ew,
                          int* __restrict__ cursor,
                          int* __restrict__ ftok, float* __restrict__ fw) {
    int t = blockIdx.x * blockDim.x + threadIdx.x;
    if (t >= NTOK) return;
#pragma unroll
    for (int s = 0; s < 2; s++) {
        int e = eidx[t * 2 + s];
        int p = atomicAdd(&cursor[e], 1);
        ftok[p] = t;
        fw[p] = ew[t * 2 + s];
    }
}

// ---------------------------------------------------------------------------
// Tiled SGEMM: C[M x Nn] = A[M x K] * B[K x Nn]  (+ epilogues)
//   128x128 tile, BK=8, 256 threads, 8x8 microtile, double-buffered smem.
//   EPI 0: C = acc (+bias)
//   EPI 1: C = gelu(acc + bias)
//   EPI 2: atomicAdd(C[token], w * (acc + bias))   (expert FC2 scatter-add)
//   EPI 3: C = acc + addv                          (Wao + residual)
//   GATHER: A row index via rowmap (negative -> zero row)
//   EXPERT: B/bias selected by per-rowblock expert id; -1 -> early exit
// ---------------------------------------------------------------------------
template <int EPI, bool GATHER, bool EXPERT>
__global__ __launch_bounds__(256)
void gemm_k(const float* __restrict__ A, const float* __restrict__ Bg,
            float* __restrict__ C, int K, int Nn,
            const float* __restrict__ biasg, const float* __restrict__ addv,
            const int* __restrict__ rowmap, const float* __restrict__ roww,
            const int* __restrict__ rbexp) {
    int e = 0;
    if (EXPERT) { e = rbexp[blockIdx.y]; if (e < 0) return; }
    const float* Bp   = Bg + (size_t)e * K * Nn;
    const float* bias = biasg ? (biasg + (size_t)e * Nn) : nullptr;

    __shared__ float As[2][8][128];
    __shared__ float Bs[2][8][128];

    int tid  = threadIdx.x;
    int tx   = tid & 15, ty = tid >> 4;
    int arow = tid >> 1;
    int akq  = (tid & 1) << 2;
    int brow = tid >> 5;
    int bcol = (tid & 31) << 2;
    int bx = blockIdx.x, by = blockIdx.y;

    int gr = by * 128 + arow;
    bool aValid = true;
    long aIdx = gr;
    if (GATHER) { int tk = rowmap[gr]; aValid = (tk >= 0); aIdx = aValid ? tk : 0; }
    const float* Aptr = A + (size_t)aIdx * K + akq;
    const float* Bptr = Bp + (size_t)brow * Nn + (size_t)bx * 128 + bcol;

    float4 aR = make_float4(0.f, 0.f, 0.f, 0.f), bR;
    if (aValid) aR = *(const float4*)Aptr;
    bR = *(const float4*)Bptr;
    As[0][akq + 0][arow] = aR.x; As[0][akq + 1][arow] = aR.y;
    As[0][akq + 2][arow] = aR.z; As[0][akq + 3][arow] = aR.w;
    *(float4*)&Bs[0][brow][bcol] = bR;
    __syncthreads();

    float acc[8][8];
#pragma unroll
    for (int i = 0; i < 8; i++)
#pragma unroll
        for (int j = 0; j < 8; j++) acc[i][j] = 0.f;

    int nt = K >> 3;
    for (int t = 0; t < nt; ++t) {
        int cur = t & 1;
        if (t + 1 < nt) {
            aR = make_float4(0.f, 0.f, 0.f, 0.f);
            if (aValid) aR = *(const float4*)(Aptr + (t + 1) * 8);
            bR = *(const float4*)(Bptr + (size_t)(t + 1) * 8 * Nn);
        }
#pragma unroll
        for (int kk = 0; kk < 8; ++kk) {
            float af[8], bf[8];
#pragma unroll
            for (int i = 0; i < 8; i++) af[i] = As[cur][kk][ty * 8 + i];
#pragma unroll
            for (int j = 0; j < 8; j++) bf[j] = Bs[cur][kk][tx * 8 + j];
#pragma unroll
            for (int i = 0; i < 8; i++)
#pragma unroll
                for (int j = 0; j < 8; j++) acc[i][j] += af[i] * bf[j];
        }
        if (t + 1 < nt) {
            int nxt = cur ^ 1;
            As[nxt][akq + 0][arow] = aR.x; As[nxt][akq + 1][arow] = aR.y;
            As[nxt][akq + 2][arow] = aR.z; As[nxt][akq + 3][arow] = aR.w;
            *(float4*)&Bs[nxt][brow][bcol] = bR;
        }
        __syncthreads();
    }

    int r0 = by * 128 + ty * 8;
    int c0 = bx * 128 + tx * 8;
    if (EPI == 2) {
#pragma unroll
        for (int i = 0; i < 8; i++) {
            int r = r0 + i;
            int tk = rowmap[r];
            if (tk < 0) continue;
            float w = roww[r];
            float* Crow = C + (size_t)tk * Nn;
#pragma unroll
            for (int j = 0; j < 8; j++) {
                float v = acc[i][j] + bias[c0 + j];
                atomicAdd(&Crow[c0 + j], w * v);
            }
        }
    } else {
#pragma unroll
        for (int i = 0; i < 8; i++) {
            int r = r0 + i;
            float* Crow = C + (size_t)r * Nn;
#pragma unroll
            for (int j = 0; j < 8; j++) {
                float v = acc[i][j];
                if (bias) v += bias[c0 + j];
                if (EPI == 1) v = gelu_f(v);
                if (EPI == 3) v += addv[(size_t)r * Nn + c0 + j];
                Crow[c0 + j] = v;
            }
        }
    }
}

// ---------------------------------------------------------------------------
// RoPE on q (reference quirk: pos*rope_freq is ELEMENTWISE -> angle depends
// only on the feature-pair index j, not the sequence position)
// ---------------------------------------------------------------------------
__global__ void rope_k(float* __restrict__ q) {
    int idx = blockIdx.x * blockDim.x + threadIdx.x;
    if (idx >= NTOK * 4 * 8) return;
    int j = idx & 7;
    int h = (idx >> 3) & 3;
    int t = idx >> 5;
    float fr  = powf(10000.f, -(float)j * 0.125f);
    float ang = (float)j * fr;
    float c = cosf(ang), s = sinf(ang);
    float* row = q + (size_t)t * 128 + h * 32;
    float x1 = row[j], x2 = row[j + 8];
    row[j]     = x1 * c - x2 * s;
    row[j + 8] = x1 * s + x2 * c;
}

// ---------------------------------------------------------------------------
// Attention: per batch (S=8, H=4, d=32), full softmax. 1 block = 1 batch,
// 32 threads, thread = (head, query_row).
// ---------------------------------------------------------------------------
__global__ void attn_k(const float* __restrict__ q, const float* __restrict__ k,
                       const float* __restrict__ v, float* __restrict__ o) {
    int b = blockIdx.x;
    int tid = threadIdx.x;
    __shared__ float sk[8 * 128], sv[8 * 128];
    const float* kb = k + (size_t)b * 8 * 128;
    const float* vb = v + (size_t)b * 8 * 128;
    for (int i = tid; i < 1024; i += 32) { sk[i] = kb[i]; sv[i] = vb[i]; }
    __syncthreads();

    int h = tid >> 3, i = tid & 7;
    const float* qr = q + ((size_t)b * 8 + i) * 128 + h * 32;
    float qreg[32];
#pragma unroll
    for (int d = 0; d < 32; d++) qreg[d] = qr[d];

    float sc[8];
#pragma unroll
    for (int j = 0; j < 8; j++) {
        float s = 0.f;
#pragma unroll
        for (int d = 0; d < 32; d++) s += qreg[d] * sk[j * 128 + h * 32 + d];
        sc[j] = s * 0.17677669529663687f;  // 1/sqrt(32)
    }
    float m = sc[0];
#pragma unroll
    for (int j = 1; j < 8; j++) m = fmaxf(m, sc[j]);
    float sum = 0.f;
#pragma unroll
    for (int j = 0; j < 8; j++) { sc[j] = expf(sc[j] - m); sum += sc[j]; }
    float inv = 1.f / sum;

    float* orow = o + ((size_t)b * 8 + i) * 128 + h * 32;
#pragma unroll
    for (int d = 0; d < 32; d++) {
        float a = 0.f;
#pragma unroll
        for (int j = 0; j < 8; j++) a += sc[j] * sv[j * 128 + h * 32 + d];
        orow[d] = a * inv;
    }
}

// ---------------------------------------------------------------------------
// Value head: out[t] = dot(comb[t], Wv) + bv
// ---------------------------------------------------------------------------
__global__ void value_k(const float* __restrict__ comb,
                        const float* __restrict__ Wv,
                        const float* __restrict__ bv,
                        float* __restrict__ out) {
    int t = blockIdx.x * blockDim.x + threadIdx.x;
    if (t >= NTOK) return;
    const float4* cr = (const float4*)(comb + (size_t)t * DIM);
    const float4* wr = (const float4*)Wv;
    float acc = 0.f;
    for (int k = 0; k < DIM / 4; k++) {
        float4 c = cr[k], w = wr[k];
        acc += c.x * w.x + c.y * w.y + c.z * w.z + c.w * w.w;
    }
    out[t] = acc + bv[0];
}

// ---------------------------------------------------------------------------
// Launcher
// ---------------------------------------------------------------------------
extern "C" void kernel_launch(void* const* d_in, const int* in_sizes, int n_in,
                              void* d_out, int out_size) {
    const float* x   = (const float*)d_in[0];
    const float* Wg  = (const float*)d_in[1];
    const float* W1  = (const float*)d_in[2];
    const float* b1  = (const float*)d_in[3];
    const float* W2  = (const float*)d_in[4];
    const float* b2  = (const float*)d_in[5];
    const float* Ws1 = (const float*)d_in[6];
    const float* bs1 = (const float*)d_in[7];
    const float* Ws2 = (const float*)d_in[8];
    const float* bs2 = (const float*)d_in[9];
    const float* rsc = (const float*)d_in[10];
    const float* Wq  = (const float*)d_in[11];
    const float* Wkv = (const float*)d_in[12];
    const float* Wku = (const float*)d_in[13];
    const float* Wvu = (const float*)d_in[14];
    const float* Wao = (const float*)d_in[15];
    const float* Wo  = (const float*)d_in[16];
    const float* bo  = (const float*)d_in[17];
    const float* Wv  = (const float*)d_in[18];
    const float* bv  = (const float*)d_in[19];
    float* outp = (float*)d_out;

    float *hs, *h, *EO, *comb, *qb, *lat, *kb, *vb, *attn, *ew, *fw;
    int *eidx, *counts, *cursor, *rbexp, *ftok;
    cudaGetSymbolAddress((void**)&hs,    g_hs);
    cudaGetSymbolAddress((void**)&h,     g_h);
    cudaGetSymbolAddress((void**)&EO,    g_EO);
    cudaGetSymbolAddress((void**)&comb,  g_comb);
    cudaGetSymbolAddress((void**)&qb,    g_q);
    cudaGetSymbolAddress((void**)&lat,   g_lat);
    cudaGetSymbolAddress((void**)&kb,    g_k);
    cudaGetSymbolAddress((void**)&vb,    g_v);
    cudaGetSymbolAddress((void**)&attn,  g_attn);
    cudaGetSymbolAddress((void**)&eidx,  g_eidx);
    cudaGetSymbolAddress((void**)&ew,    g_ew);
    cudaGetSymbolAddress((void**)&counts,g_counts);
    cudaGetSymbolAddress((void**)&cursor,g_cursor);
    cudaGetSymbolAddress((void**)&rbexp, g_rbexp);
    cudaGetSymbolAddress((void**)&ftok,  g_ftok);
    cudaGetSymbolAddress((void**)&fw,    g_fw);

    // --- routing + assignment build ---
    zero_k<<<1, 32>>>(counts);
    routing_k<<<NTOK / 128, 128>>>(x, Wg, rsc, eidx, ew, counts);
    setup_k<<<1, 256>>>(counts, cursor, rbexp, ftok);
    scatter_k<<<NTOK / 256, 256>>>(eidx, ew, cursor, ftok, fw);

    // --- shared branch: EO = gelu(x@Ws1+bs1)@Ws2 + bs2 ---
    gemm_k<1, false, false><<<dim3(FDIM / 128, NTOK / 128), 256>>>(
        x, Ws1, hs, DIM, FDIM, bs1, nullptr, nullptr, nullptr, nullptr);
    gemm_k<0, false, false><<<dim3(DIM / 128, NTOK / 128), 256>>>(
        hs, Ws2, EO, FDIM, DIM, bs2, nullptr, nullptr, nullptr, nullptr);

    // --- expert branch (grouped GEMM over 128-aligned segments) ---
    gemm_k<1, true, true><<<dim3(FDIM / 128, NRB), 256>>>(
        x, W1, h, DIM, FDIM, b1, nullptr, ftok, nullptr, rbexp);
    gemm_k<2, false, true><<<dim3(DIM / 128, NRB), 256>>>(
        h, W2, EO, FDIM, DIM, b2, nullptr, ftok, fw, rbexp);

    // --- attention projections (input = EO) ---
    gemm_k<0, false, false><<<dim3(1, NTOK / 128), 256>>>(
        EO, Wq, qb, DIM, 128, nullptr, nullptr, nullptr, nullptr, nullptr);
    gemm_k<0, false, false><<<dim3(2, NTOK / 128), 256>>>(
        EO, Wkv, lat, DIM, 256, nullptr, nullptr, nullptr, nullptr, nullptr);
    gemm_k<0, false, false><<<dim3(1, NTOK / 128), 256>>>(
        lat, Wku, kb, 256, 128, nullptr, nullptr, nullptr, nullptr, nullptr);
    gemm_k<0, false, false><<<dim3(1, NTOK / 128), 256>>>(
        lat, Wvu, vb, 256, 128, nullptr, nullptr, nullptr, nullptr, nullptr);

    rope_k<<<(NTOK * 32 + 255) / 256, 256>>>(qb);
    attn_k<<<NTOK / 8, 32>>>(qb, kb, vb, attn);

    // --- comb = EO + attn@Wao ---
    gemm_k<3, false, false><<<dim3(DIM / 128, NTOK / 128), 256>>>(
        attn, Wao, comb, 128, DIM, nullptr, EO, nullptr, nullptr, nullptr);

    // --- heads ---
    gemm_k<0, false, false><<<dim3(1024 / 128, NTOK / 128), 256>>>(
        comb, Wo, outp, DIM, 1024, bo, nullptr, nullptr, nullptr, nullptr);
    value_k<<<NTOK / 256, 256>>>(comb, Wv, bv, outp + (size_t)NTOK * 1024);
}

// round 2
// speedup vs baseline: 1.0013x; 1.0013x over previous
#include <cuda_runtime.h>
#include <math.h>

// ---------------------------------------------------------------------------
// Problem constants
//   B=2048, S=8 -> N = 16384 tokens, D = 1024, E = 8 experts, K(top)=2,
//   F = 1024, H=4, DQ=DKV=32, L=256, R=16, O=1024
// ---------------------------------------------------------------------------
#define NTOK   16384
#define DIM    1024
#define FDIM   1024
#define NEXP   8
#define NRB    264               // row-blocks for the flat (token,expert) list
#define MAXROWS (NRB * 128)      // 33792 >= 2*N + 8*127 padding

// ---------------------------------------------------------------------------
// Device scratch (static __device__ arrays: no allocation at runtime)
// ---------------------------------------------------------------------------
__device__ float g_hs  [(size_t)NTOK   * FDIM];  // shared-branch hidden
__device__ float g_h   [(size_t)MAXROWS * FDIM]; // expert hidden (flat rows)
__device__ float g_EO  [(size_t)NTOK   * DIM];   // expert_out (shared + experts)
__device__ float g_comb[(size_t)NTOK   * DIM];   // expert_out + attn_out
__device__ float g_q   [(size_t)NTOK * 128];
__device__ float g_lat [(size_t)NTOK * 256];
__device__ float g_k   [(size_t)NTOK * 128];
__device__ float g_v   [(size_t)NTOK * 128];
__device__ float g_attn[(size_t)NTOK * 128];

__device__ int   g_eidx[NTOK * 2];
__device__ float g_ew  [NTOK * 2];
__device__ int   g_counts[NEXP];
__device__ int   g_cursor[NEXP];
__device__ int   g_rbexp[NRB];      // expert id per 128-row block (-1 = unused)
__device__ int   g_ftok [MAXROWS];  // flat row -> token (-1 = padding)
__device__ float g_fw   [MAXROWS];  // flat row -> combine weight

// ---------------------------------------------------------------------------
// Helpers
// ---------------------------------------------------------------------------
__device__ __forceinline__ float gelu_f(float x) {
    return 0.5f * x * (1.0f + erff(x * 0.70710678118654752f));
}

// ---------------------------------------------------------------------------
// K0: zero per-expert counters
// ---------------------------------------------------------------------------
__global__ void zero_k(int* counts) {
    if (threadIdx.x < NEXP) counts[threadIdx.x] = 0;
}

// ---------------------------------------------------------------------------
// K1: routing — scores = sigmoid(x @ Wg) * route_scale ; top-2 ; normalize
// one thread per token; Wg (1024 x 8) staged in smem
// ---------------------------------------------------------------------------
__global__ void routing_k(const float* __restrict__ x,
                          const float* __restrict__ Wg,
                          const float* __restrict__ rsc,
                          int* __restrict__ eidx, float* __restrict__ ew,
                          int* __restrict__ counts) {
    __shared__ float sW[DIM * NEXP];  // 32 KB
    for (int i = threadIdx.x; i < DIM * NEXP; i += blockDim.x) sW[i] = Wg[i];
    __syncthreads();

    int t = blockIdx.x * blockDim.x + threadIdx.x;  // token
    float acc[NEXP];
#pragma unroll
    for (int e = 0; e < NEXP; e++) acc[e] = 0.f;

    const float* xr = x + (size_t)t * DIM;
    for (int k = 0; k < DIM; k += 4) {
        float4 xv = *(const float4*)(xr + k);
        const float* w0 = &sW[(k + 0) * NEXP];
        const float* w1 = &sW[(k + 1) * NEXP];
        const float* w2 = &sW[(k + 2) * NEXP];
        const float* w3 = &sW[(k + 3) * NEXP];
#pragma unroll
        for (int e = 0; e < NEXP; e++)
            acc[e] += xv.x * w0[e] + xv.y * w1[e] + xv.z * w2[e] + xv.w * w3[e];
    }
    float rs = rsc[0];
#pragma unroll
    for (int e = 0; e < NEXP; e++) acc[e] = rs / (1.f + expf(-acc[e]));

    // top-2 (lowest index wins on ties, matching jax top_k)
    int b0 = 0; float s0 = acc[0];
#pragma unroll
    for (int e = 1; e < NEXP; e++) if (acc[e] > s0) { s0 = acc[e]; b0 = e; }
    int b1 = -1; float s1 = -1e30f;
#pragma unroll
    for (int e = 0; e < NEXP; e++)
        if (e != b0 && acc[e] > s1) { s1 = acc[e]; b1 = e; }

    float inv = 1.f / (s0 + s1);
    eidx[t * 2 + 0] = b0; eidx[t * 2 + 1] = b1;
    ew[t * 2 + 0] = s0 * inv; ew[t * 2 + 1] = s1 * inv;
    atomicAdd(&counts[b0], 1);
    atomicAdd(&counts[b1], 1);
}

// ---------------------------------------------------------------------------
// K2: build 128-aligned per-expert segments, rowblock->expert map, cursors
// ---------------------------------------------------------------------------
__global__ void setup_k(const int* __restrict__ counts,
                        int* __restrict__ cursor,
                        int* __restrict__ rbexp,
                        int* __restrict__ ftok) {
    __shared__ int so[NEXP + 1];
    if (threadIdx.x == 0) {
        int o = 0;
        for (int e = 0; e < NEXP; e++) {
            so[e] = o;
            o += ((counts[e] + 127) >> 7) << 7;
        }
        so[NEXP] = o;
    }
    __syncthreads();
    if (threadIdx.x < NEXP) cursor[threadIdx.x] = so[threadIdx.x];
    for (int rb = threadIdx.x; rb < NRB; rb += blockDim.x) {
        int r = rb * 128, e = -1;
        for (int j = 0; j < NEXP; j++)
            if (r >= so[j] && r < so[j + 1]) e = j;
        rbexp[rb] = e;
    }
    for (int i = threadIdx.x; i < MAXROWS; i += blockDim.x) ftok[i] = -1;
}

// ---------------------------------------------------------------------------
// K3: scatter tokens into per-expert segments
// ---------------------------------------------------------------------------
__global__ void scatter_k(const int* __restrict__ eidx,
                          const float* __restrict__ ew,
                          int* __restrict__ cursor,
                          int* __restrict__ ftok, float* __restrict__ fw) {
    int t = blockIdx.x * blockDim.x + threadIdx.x;
    if (t >= NTOK) return;
#pragma unroll
    for (int s = 0; s < 2; s++) {
        int e = eidx[t * 2 + s];
        int p = atomicAdd(&cursor[e], 1);
        ftok[p] = t;
        fw[p] = ew[t * 2 + s];
    }
}

// ---------------------------------------------------------------------------
// Tiled SGEMM: C[M x Nn] = A[M x K] * B[K x Nn]  (+ epilogues)
//   128x128 tile, BK=8, 256 threads, 8x8 microtile, double-buffered smem.
//   EPI 0: C = acc (+bias)
//   EPI 1: C = gelu(acc + bias)
//   EPI 2: atomicAdd(C[token], w * (acc + bias))   (expert FC2 scatter-add)
//   EPI 3: C = acc + addv                          (Wao + residual)
//   GATHER: A row index via rowmap (negative -> zero row)
//   EXPERT: B/bias selected by per-rowblock expert id; -1 -> early exit
// ---------------------------------------------------------------------------
template <int EPI, bool GATHER, bool EXPERT>
__global__ __launch_bounds__(256)
void gemm_k(const float* __restrict__ A, const float* __restrict__ Bg,
            float* __restrict__ C, int K, int Nn,
            const float* __restrict__ biasg, const float* __restrict__ addv,
            const int* __restrict__ rowmap, const float* __restrict__ roww,
            const int* __restrict__ rbexp) {
    int e = 0;
    if (EXPERT) { e = rbexp[blockIdx.y]; if (e < 0) return; }
    const float* Bp   = Bg + (size_t)e * K * Nn;
    const float* bias = biasg ? (biasg + (size_t)e * Nn) : nullptr;

    __shared__ float As[2][8][128];
    __shared__ float Bs[2][8][128];

    int tid  = threadIdx.x;
    int tx   = tid & 15, ty = tid >> 4;
    int arow = tid >> 1;
    int akq  = (tid & 1) << 2;
    int brow = tid >> 5;
    int bcol = (tid & 31) << 2;
    int bx = blockIdx.x, by = blockIdx.y;

    int gr = by * 128 + arow;
    bool aValid = true;
    long aIdx = gr;
    if (GATHER) { int tk = rowmap[gr]; aValid = (tk >= 0); aIdx = aValid ? tk : 0; }
    const float* Aptr = A + (size_t)aIdx * K + akq;
    const float* Bptr = Bp + (size_t)brow * Nn + (size_t)bx * 128 + bcol;

    float4 aR = make_float4(0.f, 0.f, 0.f, 0.f), bR;
    if (aValid) aR = *(const float4*)Aptr;
    bR = *(const float4*)Bptr;
    As[0][akq + 0][arow] = aR.x; As[0][akq + 1][arow] = aR.y;
    As[0][akq + 2][arow] = aR.z; As[0][akq + 3][arow] = aR.w;
    *(float4*)&Bs[0][brow][bcol] = bR;
    __syncthreads();

    float acc[8][8];
#pragma unroll
    for (int i = 0; i < 8; i++)
#pragma unroll
        for (int j = 0; j < 8; j++) acc[i][j] = 0.f;

    int nt = K >> 3;
    for (int t = 0; t < nt; ++t) {
        int cur = t & 1;
        if (t + 1 < nt) {
            aR = make_float4(0.f, 0.f, 0.f, 0.f);
            if (aValid) aR = *(const float4*)(Aptr + (t + 1) * 8);
            bR = *(const float4*)(Bptr + (size_t)(t + 1) * 8 * Nn);
        }
#pragma unroll
        for (int kk = 0; kk < 8; ++kk) {
            float af[8], bf[8];
#pragma unroll
            for (int i = 0; i < 8; i++) af[i] = As[cur][kk][ty * 8 + i];
#pragma unroll
            for (int j = 0; j < 8; j++) bf[j] = Bs[cur][kk][tx * 8 + j];
#pragma unroll
            for (int i = 0; i < 8; i++)
#pragma unroll
                for (int j = 0; j < 8; j++) acc[i][j] += af[i] * bf[j];
        }
        if (t + 1 < nt) {
            int nxt = cur ^ 1;
            As[nxt][akq + 0][arow] = aR.x; As[nxt][akq + 1][arow] = aR.y;
            As[nxt][akq + 2][arow] = aR.z; As[nxt][akq + 3][arow] = aR.w;
            *(float4*)&Bs[nxt][brow][bcol] = bR;
        }
        __syncthreads();
    }

    int r0 = by * 128 + ty * 8;
    int c0 = bx * 128 + tx * 8;
    if (EPI == 2) {
#pragma unroll
        for (int i = 0; i < 8; i++) {
            int r = r0 + i;
            int tk = rowmap[r];
            if (tk < 0) continue;
            float w = roww[r];
            float* Crow = C + (size_t)tk * Nn;
#pragma unroll
            for (int j = 0; j < 8; j++) {
                float v = acc[i][j] + bias[c0 + j];
                atomicAdd(&Crow[c0 + j], w * v);
            }
        }
    } else {
#pragma unroll
        for (int i = 0; i < 8; i++) {
            int r = r0 + i;
            float* Crow = C + (size_t)r * Nn;
#pragma unroll
            for (int j = 0; j < 8; j++) {
                float v = acc[i][j];
                if (bias) v += bias[c0 + j];
                if (EPI == 1) v = gelu_f(v);
                if (EPI == 3) v += addv[(size_t)r * Nn + c0 + j];
                Crow[c0 + j] = v;
            }
        }
    }
}

// ---------------------------------------------------------------------------
// RoPE on q (reference quirk: pos*rope_freq is ELEMENTWISE -> angle depends
// only on the feature-pair index j, not the sequence position)
// ---------------------------------------------------------------------------
__global__ void rope_k(float* __restrict__ q) {
    int idx = blockIdx.x * blockDim.x + threadIdx.x;
    if (idx >= NTOK * 4 * 8) return;
    int j = idx & 7;
    int h = (idx >> 3) & 3;
    int t = idx >> 5;
    float fr  = powf(10000.f, -(float)j * 0.125f);
    float ang = (float)j * fr;
    float c = cosf(ang), s = sinf(ang);
    float* row = q + (size_t)t * 128 + h * 32;
    float x1 = row[j], x2 = row[j + 8];
    row[j]     = x1 * c - x2 * s;
    row[j + 8] = x1 * s + x2 * c;
}

// ---------------------------------------------------------------------------
// Attention: per batch (S=8, H=4, d=32), full softmax. 1 block = 1 batch,
// 32 threads, thread = (head, query_row).
// ---------------------------------------------------------------------------
__global__ void attn_k(const float* __restrict__ q, const float* __restrict__ k,
                       const float* __restrict__ v, float* __restrict__ o) {
    int b = blockIdx.x;
    int tid = threadIdx.x;
    __shared__ float sk[8 * 128], sv[8 * 128];
    const float* kb = k + (size_t)b * 8 * 128;
    const float* vb = v + (size_t)b * 8 * 128;
    for (int i = tid; i < 1024; i += 32) { sk[i] = kb[i]; sv[i] = vb[i]; }
    __syncthreads();

    int h = tid >> 3, i = tid & 7;
    const float* qr = q + ((size_t)b * 8 + i) * 128 + h * 32;
    float qreg[32];
#pragma unroll
    for (int d = 0; d < 32; d++) qreg[d] = qr[d];

    float sc[8];
#pragma unroll
    for (int j = 0; j < 8; j++) {
        float s = 0.f;
#pragma unroll
        for (int d = 0; d < 32; d++) s += qreg[d] * sk[j * 128 + h * 32 + d];
        sc[j] = s * 0.17677669529663687f;  // 1/sqrt(32)
    }
    float m = sc[0];
#pragma unroll
    for (int j = 1; j < 8; j++) m = fmaxf(m, sc[j]);
    float sum = 0.f;
#pragma unroll
    for (int j = 0; j < 8; j++) { sc[j] = expf(sc[j] - m); sum += sc[j]; }
    float inv = 1.f / sum;

    float* orow = o + ((size_t)b * 8 + i) * 128 + h * 32;
#pragma unroll
    for (int d = 0; d < 32; d++) {
        float a = 0.f;
#pragma unroll
        for (int j = 0; j < 8; j++) a += sc[j] * sv[j * 128 + h * 32 + d];
        orow[d] = a * inv;
    }
}

// ---------------------------------------------------------------------------
// Value head: out[t] = dot(comb[t], Wv) + bv
// ---------------------------------------------------------------------------
__global__ void value_k(const float* __restrict__ comb,
                        const float* __restrict__ Wv,
                        const float* __restrict__ bv,
                        float* __restrict__ out) {
    int t = blockIdx.x * blockDim.x + threadIdx.x;
    if (t >= NTOK) return;
    const float4* cr = (const float4*)(comb + (size_t)t * DIM);
    const float4* wr = (const float4*)Wv;
    float acc = 0.f;
    for (int k = 0; k < DIM / 4; k++) {
        float4 c = cr[k], w = wr[k];
        acc += c.x * w.x + c.y * w.y + c.z * w.z + c.w * w.w;
    }
    out[t] = acc + bv[0];
}

// ---------------------------------------------------------------------------
// Launcher
// ---------------------------------------------------------------------------
extern "C" void kernel_launch(void* const* d_in, const int* in_sizes, int n_in,
                              void* d_out, int out_size) {
    const float* x   = (const float*)d_in[0];
    const float* Wg  = (const float*)d_in[1];
    const float* W1  = (const float*)d_in[2];
    const float* b1  = (const float*)d_in[3];
    const float* W2  = (const float*)d_in[4];
    const float* b2  = (const float*)d_in[5];
    const float* Ws1 = (const float*)d_in[6];
    const float* bs1 = (const float*)d_in[7];
    const float* Ws2 = (const float*)d_in[8];
    const float* bs2 = (const float*)d_in[9];
    const float* rsc = (const float*)d_in[10];
    const float* Wq  = (const float*)d_in[11];
    const float* Wkv = (const float*)d_in[12];
    const float* Wku = (const float*)d_in[13];
    const float* Wvu = (const float*)d_in[14];
    const float* Wao = (const float*)d_in[15];
    const float* Wo  = (const float*)d_in[16];
    const float* bo  = (const float*)d_in[17];
    const float* Wv  = (const float*)d_in[18];
    const float* bv  = (const float*)d_in[19];
    float* outp = (float*)d_out;

    float *hs, *h, *EO, *comb, *qb, *lat, *kb, *vb, *attn, *ew, *fw;
    int *eidx, *counts, *cursor, *rbexp, *ftok;
    cudaGetSymbolAddress((void**)&hs,    g_hs);
    cudaGetSymbolAddress((void**)&h,     g_h);
    cudaGetSymbolAddress((void**)&EO,    g_EO);
    cudaGetSymbolAddress((void**)&comb,  g_comb);
    cudaGetSymbolAddress((void**)&qb,    g_q);
    cudaGetSymbolAddress((void**)&lat,   g_lat);
    cudaGetSymbolAddress((void**)&kb,    g_k);
    cudaGetSymbolAddress((void**)&vb,    g_v);
    cudaGetSymbolAddress((void**)&attn,  g_attn);
    cudaGetSymbolAddress((void**)&eidx,  g_eidx);
    cudaGetSymbolAddress((void**)&ew,    g_ew);
    cudaGetSymbolAddress((void**)&counts,g_counts);
    cudaGetSymbolAddress((void**)&cursor,g_cursor);
    cudaGetSymbolAddress((void**)&rbexp, g_rbexp);
    cudaGetSymbolAddress((void**)&ftok,  g_ftok);
    cudaGetSymbolAddress((void**)&fw,    g_fw);

    // --- routing + assignment build ---
    zero_k<<<1, 32>>>(counts);
    routing_k<<<NTOK / 128, 128>>>(x, Wg, rsc, eidx, ew, counts);
    setup_k<<<1, 256>>>(counts, cursor, rbexp, ftok);
    scatter_k<<<NTOK / 256, 256>>>(eidx, ew, cursor, ftok, fw);

    // --- shared branch: EO = gelu(x@Ws1+bs1)@Ws2 + bs2 ---
    gemm_k<1, false, false><<<dim3(FDIM / 128, NTOK / 128), 256>>>(
        x, Ws1, hs, DIM, FDIM, bs1, nullptr, nullptr, nullptr, nullptr);
    gemm_k<0, false, false><<<dim3(DIM / 128, NTOK / 128), 256>>>(
        hs, Ws2, EO, FDIM, DIM, bs2, nullptr, nullptr, nullptr, nullptr);

    // --- expert branch (grouped GEMM over 128-aligned segments) ---
    gemm_k<1, true, true><<<dim3(FDIM / 128, NRB), 256>>>(
        x, W1, h, DIM, FDIM, b1, nullptr, ftok, nullptr, rbexp);
    gemm_k<2, false, true><<<dim3(DIM / 128, NRB), 256>>>(
        h, W2, EO, FDIM, DIM, b2, nullptr, ftok, fw, rbexp);

    // --- attention projections (input = EO) ---
    gemm_k<0, false, false><<<dim3(1, NTOK / 128), 256>>>(
        EO, Wq, qb, DIM, 128, nullptr, nullptr, nullptr, nullptr, nullptr);
    gemm_k<0, false, false><<<dim3(2, NTOK / 128), 256>>>(
        EO, Wkv, lat, DIM, 256, nullptr, nullptr, nullptr, nullptr, nullptr);
    gemm_k<0, false, false><<<dim3(1, NTOK / 128), 256>>>(
        lat, Wku, kb, 256, 128, nullptr, nullptr, nullptr, nullptr, nullptr);
    gemm_k<0, false, false><<<dim3(1, NTOK / 128), 256>>>(
        lat, Wvu, vb, 256, 128, nullptr, nullptr, nullptr, nullptr, nullptr);

    rope_k<<<(NTOK * 32 + 255) / 256, 256>>>(qb);
    attn_k<<<NTOK / 8, 32>>>(qb, kb, vb, attn);

    // --- comb = EO + attn@Wao ---
    gemm_k<3, false, false><<<dim3(DIM / 128, NTOK / 128), 256>>>(
        attn, Wao, comb, 128, DIM, nullptr, EO, nullptr, nullptr, nullptr);

    // --- heads ---
    gemm_k<0, false, false><<<dim3(1024 / 128, NTOK / 128), 256>>>(
        comb, Wo, outp, DIM, 1024, bo, nullptr, nullptr, nullptr, nullptr);
    value_k<<<NTOK / 256, 256>>>(comb, Wv, bv, outp + (size_t)NTOK * 1024);
}

// round 6
// speedup vs baseline: 1.7638x; 1.7615x over previous
#include <cuda_runtime.h>
#include <math.h>
#include <stdint.h>

#define NTOK 16384
#define DIM  1024
#define FDIM 1024
#define NEXP 8
#define NRB  264
#define MAXROWS (NRB * 128)

// ---------------- device scratch ----------------
__device__ float g_hs  [(size_t)NTOK * FDIM];
__device__ float g_h   [(size_t)MAXROWS * FDIM];
__device__ float g_h2  [(size_t)MAXROWS * DIM];
__device__ float g_EO  [(size_t)NTOK * DIM];
__device__ float g_comb[(size_t)NTOK * DIM];
__device__ float g_q   [(size_t)NTOK * 128];
__device__ float g_lat [(size_t)NTOK * 256];
__device__ float g_k   [(size_t)NTOK * 128];
__device__ float g_v   [(size_t)NTOK * 128];
__device__ float g_attn[(size_t)NTOK * 128];

__device__ float g_W1T [(size_t)NEXP * FDIM * DIM];
__device__ float g_W2T [(size_t)NEXP * DIM * FDIM];
__device__ float g_Ws1T[(size_t)FDIM * DIM];
__device__ float g_Ws2T[(size_t)DIM * FDIM];
__device__ float g_WoT [(size_t)1024 * DIM];
__device__ float g_WqT [(size_t)128 * DIM];
__device__ float g_WkvT[(size_t)256 * DIM];
__device__ float g_WkuT[(size_t)128 * 256];
__device__ float g_WvuT[(size_t)128 * 256];
__device__ float g_WaoT[(size_t)DIM * 128];

__device__ int   g_eidx[NTOK * 2];
__device__ float g_ew  [NTOK * 2];
__device__ int   g_fpos[NTOK * 2];
__device__ int   g_counts[NEXP];
__device__ int   g_cursor[NEXP];
__device__ int   g_rbexp[NRB];
__device__ int   g_ftok [MAXROWS];

// ---------------- helpers ----------------
__device__ __forceinline__ uint32_t f2t(float x) {
    uint32_t r; asm("cvt.rna.tf32.f32 %0, %1;" : "=r"(r) : "f"(x)); return r;
}
__device__ __forceinline__ void mma1688(float* c, const uint32_t* a, const uint32_t* b) {
    asm volatile(
        "mma.sync.aligned.m16n8k8.row.col.f32.tf32.tf32.f32 "
        "{%0,%1,%2,%3}, {%4,%5,%6,%7}, {%8,%9}, {%0,%1,%2,%3};"
        : "+f"(c[0]), "+f"(c[1]), "+f"(c[2]), "+f"(c[3])
        : "r"(a[0]), "r"(a[1]), "r"(a[2]), "r"(a[3]), "r"(b[0]), "r"(b[1]));
}
__device__ __forceinline__ float gelu_f(float x) {
    return 0.5f * x * (1.0f + erff(x * 0.70710678118654752f));
}

// ---------------- transpose: src[K][N] -> dst[N][K] ----------------
__global__ void transpose_k(const float* __restrict__ src, float* __restrict__ dst,
                            int K, int N) {
    __shared__ float tile[32][33];
    size_t off = (size_t)blockIdx.z * K * N;
    int n0 = blockIdx.x * 32, k0 = blockIdx.y * 32;
    int tx = threadIdx.x, ty = threadIdx.y;
    for (int i = ty; i < 32; i += 8)
        tile[i][tx] = src[off + (size_t)(k0 + i) * N + n0 + tx];
    __syncthreads();
    // dst[n0+i][k0+tx] = tile[tx][i] = src[k0+tx][n0+i]  (correct transpose)
    for (int i = ty; i < 32; i += 8)
        dst[off + (size_t)(n0 + i) * K + k0 + tx] = tile[tx][i];
}

// ---------------- routing ----------------
__global__ void zero_k(int* counts) { if (threadIdx.x < NEXP) counts[threadIdx.x] = 0; }

__global__ void routing_k(const float* __restrict__ x, const float* __restrict__ Wg,
                          const float* __restrict__ rsc, int* __restrict__ eidx,
                          float* __restrict__ ew, int* __restrict__ counts) {
    __shared__ float sW[DIM * NEXP];
    for (int i = threadIdx.x; i < DIM * NEXP; i += blockDim.x) sW[i] = Wg[i];
    __syncthreads();
    int t = blockIdx.x * blockDim.x + threadIdx.x;
    float acc[NEXP];
#pragma unroll
    for (int e = 0; e < NEXP; e++) acc[e] = 0.f;
    const float* xr = x + (size_t)t * DIM;
    for (int k = 0; k < DIM; k += 4) {
        float4 xv = *(const float4*)(xr + k);
        const float* w0 = &sW[(k + 0) * NEXP];
        const float* w1 = &sW[(k + 1) * NEXP];
        const float* w2 = &sW[(k + 2) * NEXP];
        const float* w3 = &sW[(k + 3) * NEXP];
#pragma unroll
        for (int e = 0; e < NEXP; e++)
            acc[e] += xv.x * w0[e] + xv.y * w1[e] + xv.z * w2[e] + xv.w * w3[e];
    }
    float rs = rsc[0];
#pragma unroll
    for (int e = 0; e < NEXP; e++) acc[e] = rs / (1.f + expf(-acc[e]));
    int b0 = 0; float s0 = acc[0];
#pragma unroll
    for (int e = 1; e < NEXP; e++) if (acc[e] > s0) { s0 = acc[e]; b0 = e; }
    int b1 = -1; float s1 = -1e30f;
#pragma unroll
    for (int e = 0; e < NEXP; e++)
        if (e != b0 && acc[e] > s1) { s1 = acc[e]; b1 = e; }
    float inv = 1.f / (s0 + s1);
    eidx[t * 2 + 0] = b0; eidx[t * 2 + 1] = b1;
    ew[t * 2 + 0] = s0 * inv; ew[t * 2 + 1] = s1 * inv;
    atomicAdd(&counts[b0], 1);
    atomicAdd(&counts[b1], 1);
}

__global__ void setup_k(const int* __restrict__ counts, int* __restrict__ cursor,
                        int* __restrict__ rbexp, int* __restrict__ ftok) {
    __shared__ int so[NEXP + 1];
    if (threadIdx.x == 0) {
        int o = 0;
        for (int e = 0; e < NEXP; e++) { so[e] = o; o += ((counts[e] + 127) >> 7) << 7; }
        so[NEXP] = o;
    }
    __syncthreads();
    if (threadIdx.x < NEXP) cursor[threadIdx.x] = so[threadIdx.x];
    for (int rb = threadIdx.x; rb < NRB; rb += blockDim.x) {
        int r = rb * 128, e = -1;
        for (int j = 0; j < NEXP; j++)
            if (r >= so[j] && r < so[j + 1]) e = j;
        rbexp[rb] = e;
    }
    // padding rows map to token 0 (valid data, never read back)
    for (int i = threadIdx.x; i < MAXROWS; i += blockDim.x) ftok[i] = 0;
}

__global__ void scatter_k(const int* __restrict__ eidx, int* __restrict__ cursor,
                          int* __restrict__ ftok, int* __restrict__ fpos) {
    int t = blockIdx.x * blockDim.x + threadIdx.x;
    if (t >= NTOK) return;
#pragma unroll
    for (int s = 0; s < 2; s++) {
        int e = eidx[t * 2 + s];
        int p = atomicAdd(&cursor[e], 1);
        ftok[p] = t;
        fpos[t * 2 + s] = p;
    }
}

// ---------------- tf32 mma.sync GEMM ----------------
// C[M x Nn] = A[M x K] * BT[Nn x K]^T.  CTA tile 128x128, K-chunk 32.
// 8 warps: 2(M) x 4(N); warp tile 64x32 = 4x4 m16n8k8.
#define SMEM_WORDS (4 * 128 * 36)
template <int EPI, bool GATHER, bool EXPERT>
__global__ __launch_bounds__(256, 1) void tgemm(
    const float* __restrict__ A, const float* __restrict__ BT,
    float* __restrict__ C, int K, int Nn,
    const float* __restrict__ biasg, const float* __restrict__ addv,
    const int* __restrict__ rowmap, const int* __restrict__ rbexp) {
    int e = 0;
    if (EXPERT) { e = rbexp[blockIdx.y]; if (e < 0) return; }
    const float* Bp   = BT + (size_t)e * Nn * K;
    const float* bias = biasg ? biasg + (size_t)e * Nn : nullptr;

    extern __shared__ uint32_t sm[];
    uint32_t* AsB[2] = { sm, sm + 4608 };
    uint32_t* BsB[2] = { sm + 9216, sm + 13824 };

    int tid = threadIdx.x, lane = tid & 31, wid = tid >> 5;
    int wm = wid & 1, wn = wid >> 1;
    int tr = lane >> 2, tc = lane & 3;

    int arow  = tid >> 1;
    int kbase = (tid & 1) * 16;
    int gr = blockIdx.y * 128 + arow;
    long aIdx = gr;
    if (GATHER) { int tk = rowmap[gr]; aIdx = tk < 0 ? 0 : tk; }
    const float* Aptr = A + (size_t)aIdx * K + kbase;
    const float* Bptr = Bp + (size_t)(blockIdx.x * 128 + arow) * K + kbase;
    uint32_t* aDst0 = AsB[0] + arow * 36 + kbase;
    uint32_t* aDst1 = AsB[1] + arow * 36 + kbase;
    uint32_t* bDst0 = BsB[0] + arow * 36 + kbase;
    uint32_t* bDst1 = BsB[1] + arow * 36 + kbase;

    float acc[4][4][4];
#pragma unroll
    for (int i = 0; i < 4; i++)
#pragma unroll
        for (int j = 0; j < 4; j++)
#pragma unroll
            for (int r = 0; r < 4; r++) acc[i][j][r] = 0.f;

    uint4 ar[4], br[4];
#pragma unroll
    for (int i = 0; i < 4; i++) {
        float4 va = *(const float4*)(Aptr + i * 4);
        float4 vb = *(const float4*)(Bptr + i * 4);
        ar[i].x = f2t(va.x); ar[i].y = f2t(va.y); ar[i].z = f2t(va.z); ar[i].w = f2t(va.w);
        br[i].x = f2t(vb.x); br[i].y = f2t(vb.y); br[i].z = f2t(vb.z); br[i].w = f2t(vb.w);
    }
#pragma unroll
    for (int i = 0; i < 4; i++) {
        *(uint4*)(aDst0 + i * 4) = ar[i];
        *(uint4*)(bDst0 + i * 4) = br[i];
    }
    __syncthreads();

    int NC = K >> 5;
    for (int c = 0; c < NC; c++) {
        int buf = c & 1;
        if (c + 1 < NC) {
            int ko = (c + 1) * 32;
#pragma unroll
            for (int i = 0; i < 4; i++) {
                float4 va = *(const float4*)(Aptr + ko + i * 4);
                float4 vb = *(const float4*)(Bptr + ko + i * 4);
                ar[i].x = f2t(va.x); ar[i].y = f2t(va.y);
                ar[i].z = f2t(va.z); ar[i].w = f2t(va.w);
                br[i].x = f2t(vb.x); br[i].y = f2t(vb.y);
                br[i].z = f2t(vb.z); br[i].w = f2t(vb.w);
            }
        }
        const uint32_t* Ab = AsB[buf];
        const uint32_t* Bb = BsB[buf];
#pragma unroll
        for (int ks = 0; ks < 4; ks++) {
            int kk = ks * 8;
            uint32_t af[4][4], bf[4][2];
#pragma unroll
            for (int mi = 0; mi < 4; mi++) {
                const uint32_t* p = Ab + (wm * 64 + mi * 16 + tr) * 36 + kk + tc;
                af[mi][0] = p[0];
                af[mi][1] = p[8 * 36];
                af[mi][2] = p[4];
                af[mi][3] = p[8 * 36 + 4];
            }
#pragma unroll
            for (int ni = 0; ni < 4; ni++) {
                const uint32_t* p = Bb + (wn * 32 + ni * 8 + tr) * 36 + kk + tc;
                bf[ni][0] = p[0];
                bf[ni][1] = p[4];
            }
#pragma unroll
            for (int mi = 0; mi < 4; mi++)
#pragma unroll
                for (int ni = 0; ni < 4; ni++)
                    mma1688(acc[mi][ni], af[mi], bf[ni]);
        }
        if (c + 1 < NC) {
            uint32_t* ad = (buf ? aDst0 : aDst1);
            uint32_t* bd = (buf ? bDst0 : bDst1);
#pragma unroll
            for (int i = 0; i < 4; i++) {
                *(uint4*)(ad + i * 4) = ar[i];
                *(uint4*)(bd + i * 4) = br[i];
            }
            __syncthreads();
        }
    }

    // epilogue
    int tc2 = tc * 2;
#pragma unroll
    for (int mi = 0; mi < 4; mi++) {
#pragma unroll
        for (int ni = 0; ni < 4; ni++) {
            int r0 = blockIdx.y * 128 + wm * 64 + mi * 16 + tr;
            int cg = blockIdx.x * 128 + wn * 32 + ni * 8 + tc2;
#pragma unroll
            for (int half = 0; half < 2; half++) {
                int r = r0 + half * 8;
                float v0 = acc[mi][ni][half * 2 + 0];
                float v1 = acc[mi][ni][half * 2 + 1];
                if (bias) { v0 += bias[cg]; v1 += bias[cg + 1]; }
                if (EPI == 1) { v0 = gelu_f(v0); v1 = gelu_f(v1); }
                if (EPI == 3) {
                    const float* arow2 = addv + (size_t)r * Nn + cg;
                    v0 += arow2[0]; v1 += arow2[1];
                }
                *(float2*)(C + (size_t)r * Nn + cg) = make_float2(v0, v1);
            }
        }
    }
}

// ---------------- MoE combine ----------------
__global__ void combine_k(float* __restrict__ EO, const float* __restrict__ h2,
                          const int* __restrict__ fpos, const float* __restrict__ ew) {
    int t = blockIdx.x;
    float w0 = ew[t * 2], w1 = ew[t * 2 + 1];
    const float4* r0 = (const float4*)(h2 + (size_t)fpos[t * 2] * DIM);
    const float4* r1 = (const float4*)(h2 + (size_t)fpos[t * 2 + 1] * DIM);
    float4* eo = (float4*)(EO + (size_t)t * DIM);
    int i = threadIdx.x;
    float4 a = eo[i], b = r0[i], c = r1[i];
    a.x += w0 * b.x + w1 * c.x; a.y += w0 * b.y + w1 * c.y;
    a.z += w0 * b.z + w1 * c.z; a.w += w0 * b.w + w1 * c.w;
    eo[i] = a;
}

// ---------------- RoPE (reference quirk: angle depends only on pair index) --
__global__ void rope_k(float* __restrict__ q) {
    int idx = blockIdx.x * blockDim.x + threadIdx.x;
    if (idx >= NTOK * 4 * 8) return;
    int j = idx & 7, h = (idx >> 3) & 3, t = idx >> 5;
    float fr = powf(10000.f, -(float)j * 0.125f);
    float ang = (float)j * fr;
    float c = cosf(ang), s = sinf(ang);
    float* row = q + (size_t)t * 128 + h * 32;
    float x1 = row[j], x2 = row[j + 8];
    row[j] = x1 * c - x2 * s;
    row[j + 8] = x1 * s + x2 * c;
}

// ---------------- attention (per batch: S=8, H=4, d=32) ----------------
__global__ void attn_k(const float* __restrict__ q, const float* __restrict__ k,
                       const float* __restrict__ v, float* __restrict__ o) {
    int b = blockIdx.x, tid = threadIdx.x;
    __shared__ float sk[1024], sv[1024];
    const float* kb = k + (size_t)b * 1024;
    const float* vb = v + (size_t)b * 1024;
    for (int i = tid; i < 1024; i += 32) { sk[i] = kb[i]; sv[i] = vb[i]; }
    __syncthreads();
    int h = tid >> 3, i = tid & 7;
    const float* qr = q + ((size_t)b * 8 + i) * 128 + h * 32;
    float qreg[32];
#pragma unroll
    for (int d = 0; d < 32; d++) qreg[d] = qr[d];
    float sc[8];
#pragma unroll
    for (int j = 0; j < 8; j++) {
        float s = 0.f;
#pragma unroll
        for (int d = 0; d < 32; d++) s += qreg[d] * sk[j * 128 + h * 32 + d];
        sc[j] = s * 0.17677669529663687f;
    }
    float m = sc[0];
#pragma unroll
    for (int j = 1; j < 8; j++) m = fmaxf(m, sc[j]);
    float sum = 0.f;
#pragma unroll
    for (int j = 0; j < 8; j++) { sc[j] = expf(sc[j] - m); sum += sc[j]; }
    float inv = 1.f / sum;
    float* orow = o + ((size_t)b * 8 + i) * 128 + h * 32;
#pragma unroll
    for (int d = 0; d < 32; d++) {
        float a = 0.f;
#pragma unroll
        for (int j = 0; j < 8; j++) a += sc[j] * sv[j * 128 + h * 32 + d];
        orow[d] = a * inv;
    }
}

// ---------------- value head ----------------
__global__ void value_k(const float* __restrict__ comb, const float* __restrict__ Wv,
                        const float* __restrict__ bv, float* __restrict__ out) {
    int t = blockIdx.x * blockDim.x + threadIdx.x;
    if (t >= NTOK) return;
    const float4* cr = (const float4*)(comb + (size_t)t * DIM);
    const float4* wr = (const float4*)Wv;
    float acc = 0.f;
    for (int k = 0; k < DIM / 4; k++) {
        float4 c = cr[k], w = wr[k];
        acc += c.x * w.x + c.y * w.y + c.z * w.z + c.w * w.w;
    }
    out[t] = acc + bv[0];
}

// ---------------- launcher ----------------
#define SMEMB (SMEM_WORDS * 4)

extern "C" void kernel_launch(void* const* d_in, const int* in_sizes, int n_in,
                              void* d_out, int out_size) {
    const float* x   = (const float*)d_in[0];
    const float* Wg  = (const float*)d_in[1];
    const float* W1  = (const float*)d_in[2];
    const float* b1  = (const float*)d_in[3];
    const float* W2  = (const float*)d_in[4];
    const float* b2  = (const float*)d_in[5];
    const float* Ws1 = (const float*)d_in[6];
    const float* bs1 = (const float*)d_in[7];
    const float* Ws2 = (const float*)d_in[8];
    const float* bs2 = (const float*)d_in[9];
    const float* rsc = (const float*)d_in[10];
    const float* Wq  = (const float*)d_in[11];
    const float* Wkv = (const float*)d_in[12];
    const float* Wku = (const float*)d_in[13];
    const float* Wvu = (const float*)d_in[14];
    const float* Wao = (const float*)d_in[15];
    const float* Wo  = (const float*)d_in[16];
    const float* bo  = (const float*)d_in[17];
    const float* Wv  = (const float*)d_in[18];
    const float* bv  = (const float*)d_in[19];
    float* outp = (float*)d_out;

    float *hs, *h, *h2, *EO, *comb, *qb, *lat, *kb, *vb, *attn, *ew;
    float *W1T, *W2T, *Ws1T, *Ws2T, *WoT, *WqT, *WkvT, *WkuT, *WvuT, *WaoT;
    int *eidx, *fpos, *counts, *cursor, *rbexp, *ftok;
    cudaGetSymbolAddress((void**)&hs, g_hs);
    cudaGetSymbolAddress((void**)&h, g_h);
    cudaGetSymbolAddress((void**)&h2, g_h2);
    cudaGetSymbolAddress((void**)&EO, g_EO);
    cudaGetSymbolAddress((void**)&comb, g_comb);
    cudaGetSymbolAddress((void**)&qb, g_q);
    cudaGetSymbolAddress((void**)&lat, g_lat);
    cudaGetSymbolAddress((void**)&kb, g_k);
    cudaGetSymbolAddress((void**)&vb, g_v);
    cudaGetSymbolAddress((void**)&attn, g_attn);
    cudaGetSymbolAddress((void**)&ew, g_ew);
    cudaGetSymbolAddress((void**)&W1T, g_W1T);
    cudaGetSymbolAddress((void**)&W2T, g_W2T);
    cudaGetSymbolAddress((void**)&Ws1T, g_Ws1T);
    cudaGetSymbolAddress((void**)&Ws2T, g_Ws2T);
    cudaGetSymbolAddress((void**)&WoT, g_WoT);
    cudaGetSymbolAddress((void**)&WqT, g_WqT);
    cudaGetSymbolAddress((void**)&WkvT, g_WkvT);
    cudaGetSymbolAddress((void**)&WkuT, g_WkuT);
    cudaGetSymbolAddress((void**)&WvuT, g_WvuT);
    cudaGetSymbolAddress((void**)&WaoT, g_WaoT);
    cudaGetSymbolAddress((void**)&eidx, g_eidx);
    cudaGetSymbolAddress((void**)&fpos, g_fpos);
    cudaGetSymbolAddress((void**)&counts, g_counts);
    cudaGetSymbolAddress((void**)&cursor, g_cursor);
    cudaGetSymbolAddress((void**)&rbexp, g_rbexp);
    cudaGetSymbolAddress((void**)&ftok, g_ftok);

    cudaFuncSetAttribute(tgemm<1, false, false>,
                         cudaFuncAttributeMaxDynamicSharedMemorySize, SMEMB);
    cudaFuncSetAttribute(tgemm<0, false, false>,
                         cudaFuncAttributeMaxDynamicSharedMemorySize, SMEMB);
    cudaFuncSetAttribute(tgemm<1, true, true>,
                         cudaFuncAttributeMaxDynamicSharedMemorySize, SMEMB);
    cudaFuncSetAttribute(tgemm<0, false, true>,
                         cudaFuncAttributeMaxDynamicSharedMemorySize, SMEMB);
    cudaFuncSetAttribute(tgemm<3, false, false>,
                         cudaFuncAttributeMaxDynamicSharedMemorySize, SMEMB);

    dim3 tb(32, 8);
    transpose_k<<<dim3(32, 32, NEXP), tb>>>(W1, W1T, DIM, FDIM);
    transpose_k<<<dim3(32, 32, NEXP), tb>>>(W2, W2T, FDIM, DIM);
    transpose_k<<<dim3(32, 32, 1), tb>>>(Ws1, Ws1T, DIM, FDIM);
    transpose_k<<<dim3(32, 32, 1), tb>>>(Ws2, Ws2T, FDIM, DIM);
    transpose_k<<<dim3(32, 32, 1), tb>>>(Wo, WoT, DIM, 1024);
    transpose_k<<<dim3(4, 32, 1), tb>>>(Wq, WqT, DIM, 128);
    transpose_k<<<dim3(8, 32, 1), tb>>>(Wkv, WkvT, DIM, 256);
    transpose_k<<<dim3(4, 8, 1), tb>>>(Wku, WkuT, 256, 128);
    transpose_k<<<dim3(4, 8, 1), tb>>>(Wvu, WvuT, 256, 128);
    transpose_k<<<dim3(32, 4, 1), tb>>>(Wao, WaoT, 128, 1024);

    zero_k<<<1, 32>>>(counts);
    routing_k<<<NTOK / 128, 128>>>(x, Wg, rsc, eidx, ew, counts);
    setup_k<<<1, 256>>>(counts, cursor, rbexp, ftok);
    scatter_k<<<NTOK / 256, 256>>>(eidx, cursor, ftok, fpos);

    // shared branch -> EO
    tgemm<1, false, false><<<dim3(8, 128), 256, SMEMB>>>(
        x, Ws1T, hs, DIM, FDIM, bs1, nullptr, nullptr, nullptr);
    tgemm<0, false, false><<<dim3(8, 128), 256, SMEMB>>>(
        hs, Ws2T, EO, FDIM, DIM, bs2, nullptr, nullptr, nullptr);

    // expert branch (grouped over 128-aligned segments) -> flat h2 -> combine
    tgemm<1, true, true><<<dim3(8, NRB), 256, SMEMB>>>(
        x, W1T, h, DIM, FDIM, b1, nullptr, ftok, rbexp);
    tgemm<0, false, true><<<dim3(8, NRB), 256, SMEMB>>>(
        h, W2T, h2, FDIM, DIM, b2, nullptr, nullptr, rbexp);
    combine_k<<<NTOK, 256>>>(EO, h2, fpos, ew);

    // attention projections
    tgemm<0, false, false><<<dim3(1, 128), 256, SMEMB>>>(
        EO, WqT, qb, DIM, 128, nullptr, nullptr, nullptr, nullptr);
    tgemm<0, false, false><<<dim3(2, 128), 256, SMEMB>>>(
        EO, WkvT, lat, DIM, 256, nullptr, nullptr, nullptr, nullptr);
    tgemm<0, false, false><<<dim3(1, 128), 256, SMEMB>>>(
        lat, WkuT, kb, 256, 128, nullptr, nullptr, nullptr, nullptr);
    tgemm<0, false, false><<<dim3(1, 128), 256, SMEMB>>>(
        lat, WvuT, vb, 256, 128, nullptr, nullptr, nullptr, nullptr);

    rope_k<<<(NTOK * 32 + 255) / 256, 256>>>(qb);
    attn_k<<<NTOK / 8, 32>>>(qb, kb, vb, attn);

    // comb = EO + attn @ Wao
    tgemm<3, false, false><<<dim3(8, 128), 256, SMEMB>>>(
        attn, WaoT, comb, 128, DIM, nullptr, EO, nullptr, nullptr);

    // heads
    tgemm<0, false, false><<<dim3(8, 128), 256, SMEMB>>>(
        comb, WoT, outp, DIM, 1024, bo, nullptr, nullptr, nullptr);
    value_k<<<NTOK / 256, 256>>>(comb, Wv, bv, outp + (size_t)NTOK * 1024);
}

// round 11
// speedup vs baseline: 3.5488x; 2.0120x over previous
// fp16 mma.sync pipeline — resubmission (R7/R9/R10 container flakes; R8 proved
// this structure reaches the toolchain). Semantic content identical to R9.
#include <cuda_runtime.h>
#include <cuda_fp16.h>
#include <math.h>
#include <stdint.h>

#define NTOK 16384
#define DIM  1024
#define FDIM 1024
#define NEXP 8
#define NRB  264
#define MAXROWS (NRB * 128)

// ---------------- device scratch ----------------
__device__ float g_hs  [(size_t)NTOK * FDIM];
__device__ float g_h   [(size_t)MAXROWS * FDIM];
__device__ float g_h2  [(size_t)MAXROWS * DIM];
__device__ float g_EO  [(size_t)NTOK * DIM];
__device__ float g_comb[(size_t)NTOK * DIM];
__device__ float g_q   [(size_t)NTOK * 128];
__device__ float g_lat [(size_t)NTOK * 256];
__device__ float g_k   [(size_t)NTOK * 128];
__device__ float g_v   [(size_t)NTOK * 128];
__device__ float g_attn[(size_t)NTOK * 128];

// fp16 transposed weights, [N][K] K-major
__device__ half g_W1T [(size_t)NEXP * FDIM * DIM];
__device__ half g_W2T [(size_t)NEXP * DIM * FDIM];
__device__ half g_Ws1T[(size_t)FDIM * DIM];
__device__ half g_Ws2T[(size_t)DIM * FDIM];
__device__ half g_WoT [(size_t)1024 * DIM];
__device__ half g_WqT [(size_t)128 * DIM];
__device__ half g_WkvT[(size_t)256 * DIM];
__device__ half g_WkuT[(size_t)128 * 256];
__device__ half g_WvuT[(size_t)128 * 256];
__device__ half g_WaoT[(size_t)DIM * 128];

__device__ int   g_eidx[NTOK * 2];
__device__ float g_ew  [NTOK * 2];
__device__ int   g_fpos[NTOK * 2];
__device__ int   g_counts[NEXP];
__device__ int   g_cursor[NEXP];
__device__ int   g_rbexp[NRB];
__device__ int   g_ftok [MAXROWS];

// ---------------- helpers ----------------
__device__ __forceinline__ uint32_t f22h(float x, float y) {
    __half2 h = __floats2half2_rn(x, y);
    return *(uint32_t*)&h;
}
__device__ __forceinline__ void mma16816(float* c, const uint32_t* a, const uint32_t* b) {
    asm volatile(
        "mma.sync.aligned.m16n8k16.row.col.f32.f16.f16.f32 "
        "{%0,%1,%2,%3}, {%4,%5,%6,%7}, {%8,%9}, {%0,%1,%2,%3};"
        : "+f"(c[0]), "+f"(c[1]), "+f"(c[2]), "+f"(c[3])
        : "r"(a[0]), "r"(a[1]), "r"(a[2]), "r"(a[3]), "r"(b[0]), "r"(b[1]));
}
__device__ __forceinline__ float gelu_f(float x) {
    return 0.5f * x * (1.0f + erff(x * 0.70710678118654752f));
}

// ---------------- transpose+convert: src[K][N] f32 -> dst[N][K] f16 --------
__global__ void transpose_h(const float* __restrict__ src, half* __restrict__ dst,
                            int K, int N) {
    __shared__ float tile[32][33];
    size_t off = (size_t)blockIdx.z * K * N;
    int n0 = blockIdx.x * 32, k0 = blockIdx.y * 32;
    int tx = threadIdx.x, ty = threadIdx.y;
    for (int i = ty; i < 32; i += 8)
        tile[i][tx] = src[off + (size_t)(k0 + i) * N + n0 + tx];
    __syncthreads();
    for (int i = ty; i < 32; i += 8)
        dst[off + (size_t)(n0 + i) * K + k0 + tx] = __float2half(tile[tx][i]);
}

// ---------------- routing ----------------
__global__ void zero_k(int* counts) { if (threadIdx.x < NEXP) counts[threadIdx.x] = 0; }

__global__ void routing_k(const float* __restrict__ x, const float* __restrict__ Wg,
                          const float* __restrict__ rsc, int* __restrict__ eidx,
                          float* __restrict__ ew, int* __restrict__ counts) {
    __shared__ float sW[DIM * NEXP];
    for (int i = threadIdx.x; i < DIM * NEXP; i += blockDim.x) sW[i] = Wg[i];
    __syncthreads();
    int t = blockIdx.x * blockDim.x + threadIdx.x;
    float acc[NEXP];
#pragma unroll
    for (int e = 0; e < NEXP; e++) acc[e] = 0.f;
    const float* xr = x + (size_t)t * DIM;
    for (int k = 0; k < DIM; k += 4) {
        float4 xv = *(const float4*)(xr + k);
        const float* w0 = &sW[(k + 0) * NEXP];
        const float* w1 = &sW[(k + 1) * NEXP];
        const float* w2 = &sW[(k + 2) * NEXP];
        const float* w3 = &sW[(k + 3) * NEXP];
#pragma unroll
        for (int e = 0; e < NEXP; e++)
            acc[e] += xv.x * w0[e] + xv.y * w1[e] + xv.z * w2[e] + xv.w * w3[e];
    }
    float rs = rsc[0];
#pragma unroll
    for (int e = 0; e < NEXP; e++) acc[e] = rs / (1.f + expf(-acc[e]));
    int b0 = 0; float s0 = acc[0];
#pragma unroll
    for (int e = 1; e < NEXP; e++) if (acc[e] > s0) { s0 = acc[e]; b0 = e; }
    int b1 = -1; float s1 = -1e30f;
#pragma unroll
    for (int e = 0; e < NEXP; e++)
        if (e != b0 && acc[e] > s1) { s1 = acc[e]; b1 = e; }
    float inv = 1.f / (s0 + s1);
    eidx[t * 2 + 0] = b0; eidx[t * 2 + 1] = b1;
    ew[t * 2 + 0] = s0 * inv; ew[t * 2 + 1] = s1 * inv;
    atomicAdd(&counts[b0], 1);
    atomicAdd(&counts[b1], 1);
}

__global__ void setup_k(const int* __restrict__ counts, int* __restrict__ cursor,
                        int* __restrict__ rbexp, int* __restrict__ ftok) {
    __shared__ int so[NEXP + 1];
    if (threadIdx.x == 0) {
        int o = 0;
        for (int e = 0; e < NEXP; e++) { so[e] = o; o += ((counts[e] + 127) >> 7) << 7; }
        so[NEXP] = o;
    }
    __syncthreads();
    if (threadIdx.x < NEXP) cursor[threadIdx.x] = so[threadIdx.x];
    for (int rb = threadIdx.x; rb < NRB; rb += blockDim.x) {
        int r = rb * 128, e = -1;
        for (int j = 0; j < NEXP; j++)
            if (r >= so[j] && r < so[j + 1]) e = j;
        rbexp[rb] = e;
    }
    for (int i = threadIdx.x; i < MAXROWS; i += blockDim.x) ftok[i] = 0;
}

__global__ void scatter_k(const int* __restrict__ eidx, int* __restrict__ cursor,
                          int* __restrict__ ftok, int* __restrict__ fpos) {
    int t = blockIdx.x * blockDim.x + threadIdx.x;
    if (t >= NTOK) return;
#pragma unroll
    for (int s = 0; s < 2; s++) {
        int e = eidx[t * 2 + s];
        int p = atomicAdd(&cursor[e], 1);
        ftok[p] = t;
        fpos[t * 2 + s] = p;
    }
}

// ---------------- fp16 mma.sync GEMM ----------------
// C[M x Nn] = A[M x K](f32 in, cvt at stage) * BT[Nn x K](f16)^T.
// CTA tile 128x128, K-chunk 32 (2 x k16). 8 warps 2(M)x4(N), warp tile 64x32.
// 40-half row pitch keeps all fragment loads bank-conflict-free.
template <int EPI, bool GATHER, bool EXPERT>
__global__ __launch_bounds__(256, 2) void tgemm(
    const float* __restrict__ A, const half* __restrict__ BT,
    float* __restrict__ C, int K, int Nn,
    const float* __restrict__ biasg, const float* __restrict__ addv,
    const int* __restrict__ rowmap, const int* __restrict__ rbexp) {
    int e = 0;
    if (EXPERT) { e = rbexp[blockIdx.y]; if (e < 0) return; }
    const half* Bp    = BT + (size_t)e * Nn * K;
    const float* bias = biasg ? biasg + (size_t)e * Nn : nullptr;

    __shared__ half As[2][128][40];
    __shared__ half Bs[2][128][40];

    int tid = threadIdx.x, lane = tid & 31, wid = tid >> 5;
    int wm = wid & 1, wn = wid >> 1;
    int tr = lane >> 2, tc = lane & 3;

    int arow = tid >> 1;
    int kb   = (tid & 1) * 16;
    int gr = blockIdx.y * 128 + arow;
    long aIdx = gr;
    if (GATHER) { int tk = rowmap[gr]; aIdx = tk < 0 ? 0 : tk; }
    const float* Aptr = A + (size_t)aIdx * K + kb;
    const half*  Bptr = Bp + (size_t)(blockIdx.x * 128 + arow) * K + kb;

    float acc[4][4][4];
#pragma unroll
    for (int i = 0; i < 4; i++)
#pragma unroll
        for (int j = 0; j < 4; j++)
#pragma unroll
            for (int r = 0; r < 4; r++) acc[i][j][r] = 0.f;

    float4 ar[4]; uint4 br[2];
#pragma unroll
    for (int i = 0; i < 4; i++) ar[i] = *(const float4*)(Aptr + i * 4);
    br[0] = *(const uint4*)(Bptr);
    br[1] = *(const uint4*)(Bptr + 8);
    {
        uint4 pa0 = make_uint4(f22h(ar[0].x, ar[0].y), f22h(ar[0].z, ar[0].w),
                               f22h(ar[1].x, ar[1].y), f22h(ar[1].z, ar[1].w));
        uint4 pa1 = make_uint4(f22h(ar[2].x, ar[2].y), f22h(ar[2].z, ar[2].w),
                               f22h(ar[3].x, ar[3].y), f22h(ar[3].z, ar[3].w));
        *(uint4*)&As[0][arow][kb]     = pa0;
        *(uint4*)&As[0][arow][kb + 8] = pa1;
        *(uint4*)&Bs[0][arow][kb]     = br[0];
        *(uint4*)&Bs[0][arow][kb + 8] = br[1];
    }
    __syncthreads();

    int NC = K >> 5;
    for (int c = 0; c < NC; c++) {
        int buf = c & 1;
        if (c + 1 < NC) {
            int ko = (c + 1) * 32;
#pragma unroll
            for (int i = 0; i < 4; i++) ar[i] = *(const float4*)(Aptr + ko + i * 4);
            br[0] = *(const uint4*)(Bptr + ko);
            br[1] = *(const uint4*)(Bptr + ko + 8);
        }
#pragma unroll
        for (int ks = 0; ks < 2; ks++) {
            int kk = ks * 16 + tc * 2;
            uint32_t af[4][4], bf[4][2];
#pragma unroll
            for (int mi = 0; mi < 4; mi++) {
                int m0 = wm * 64 + mi * 16 + tr;
                af[mi][0] = *(const uint32_t*)&As[buf][m0][kk];
                af[mi][1] = *(const uint32_t*)&As[buf][m0 + 8][kk];
                af[mi][2] = *(const uint32_t*)&As[buf][m0][kk + 8];
                af[mi][3] = *(const uint32_t*)&As[buf][m0 + 8][kk + 8];
            }
#pragma unroll
            for (int ni = 0; ni < 4; ni++) {
                int n0 = wn * 32 + ni * 8 + tr;
                bf[ni][0] = *(const uint32_t*)&Bs[buf][n0][kk];
                bf[ni][1] = *(const uint32_t*)&Bs[buf][n0][kk + 8];
            }
#pragma unroll
            for (int mi = 0; mi < 4; mi++)
#pragma unroll
                for (int ni = 0; ni < 4; ni++)
                    mma16816(acc[mi][ni], af[mi], bf[ni]);
        }
        if (c + 1 < NC) {
            int nb = buf ^ 1;
            uint4 pa0 = make_uint4(f22h(ar[0].x, ar[0].y), f22h(ar[0].z, ar[0].w),
                                   f22h(ar[1].x, ar[1].y), f22h(ar[1].z, ar[1].w));
            uint4 pa1 = make_uint4(f22h(ar[2].x, ar[2].y), f22h(ar[2].z, ar[2].w),
                                   f22h(ar[3].x, ar[3].y), f22h(ar[3].z, ar[3].w));
            *(uint4*)&As[nb][arow][kb]     = pa0;
            *(uint4*)&As[nb][arow][kb + 8] = pa1;
            *(uint4*)&Bs[nb][arow][kb]     = br[0];
            *(uint4*)&Bs[nb][arow][kb + 8] = br[1];
            __syncthreads();
        }
    }

    // epilogue: bias / gelu / residual fused on the f32 accumulators
    int tc2 = tc * 2;
#pragma unroll
    for (int mi = 0; mi < 4; mi++) {
#pragma unroll
        for (int ni = 0; ni < 4; ni++) {
            int r0 = blockIdx.y * 128 + wm * 64 + mi * 16 + tr;
            int cg = blockIdx.x * 128 + wn * 32 + ni * 8 + tc2;
#pragma unroll
            for (int half_ = 0; half_ < 2; half_++) {
                int r = r0 + half_ * 8;
                float v0 = acc[mi][ni][half_ * 2 + 0];
                float v1 = acc[mi][ni][half_ * 2 + 1];
                if (bias) { v0 += bias[cg]; v1 += bias[cg + 1]; }
                if (EPI == 1) { v0 = gelu_f(v0); v1 = gelu_f(v1); }
                if (EPI == 3) {
                    const float* arow2 = addv + (size_t)r * Nn + cg;
                    v0 += arow2[0]; v1 += arow2[1];
                }
                *(float2*)(C + (size_t)r * Nn + cg) = make_float2(v0, v1);
            }
        }
    }
}

// ---------------- MoE combine (atomic-free gather of the 2 expert rows) ----
__global__ void combine_k(float* __restrict__ EO, const float* __restrict__ h2,
                          const int* __restrict__ fpos, const float* __restrict__ ew) {
    int t = blockIdx.x;
    float w0 = ew[t * 2], w1 = ew[t * 2 + 1];
    const float4* r0 = (const float4*)(h2 + (size_t)fpos[t * 2] * DIM);
    const float4* r1 = (const float4*)(h2 + (size_t)fpos[t * 2 + 1] * DIM);
    float4* eo = (float4*)(EO + (size_t)t * DIM);
    int i = threadIdx.x;
    float4 a = eo[i], b = r0[i], c = r1[i];
    a.x += w0 * b.x + w1 * c.x; a.y += w0 * b.y + w1 * c.y;
    a.z += w0 * b.z + w1 * c.z; a.w += w0 * b.w + w1 * c.w;
    eo[i] = a;
}

// ---------------- RoPE (reference quirk: angle depends only on pair index) --
__global__ void rope_k(float* __restrict__ q) {
    int idx = blockIdx.x * blockDim.x + threadIdx.x;
    if (idx >= NTOK * 4 * 8) return;
    int j = idx & 7, h = (idx >> 3) & 3, t = idx >> 5;
    float fr = powf(10000.f, -(float)j * 0.125f);
    float ang = (float)j * fr;
    float c = cosf(ang), s = sinf(ang);
    float* row = q + (size_t)t * 128 + h * 32;
    float x1 = row[j], x2 = row[j + 8];
    row[j] = x1 * c - x2 * s;
    row[j + 8] = x1 * s + x2 * c;
}

// ---------------- attention (per batch: S=8, H=4, d=32) ----------------
__global__ void attn_k(const float* __restrict__ q, const float* __restrict__ k,
                       const float* __restrict__ v, float* __restrict__ o) {
    int b = blockIdx.x, tid = threadIdx.x;
    __shared__ float sk[1024], sv[1024];
    const float* kb = k + (size_t)b * 1024;
    const float* vb = v + (size_t)b * 1024;
    for (int i = tid; i < 1024; i += 32) { sk[i] = kb[i]; sv[i] = vb[i]; }
    __syncthreads();
    int h = tid >> 3, i = tid & 7;
    const float* qr = q + ((size_t)b * 8 + i) * 128 + h * 32;
    float qreg[32];
#pragma unroll
    for (int d = 0; d < 32; d++) qreg[d] = qr[d];
    float sc[8];
#pragma unroll
    for (int j = 0; j < 8; j++) {
        float s = 0.f;
#pragma unroll
        for (int d = 0; d < 32; d++) s += qreg[d] * sk[j * 128 + h * 32 + d];
        sc[j] = s * 0.17677669529663687f;
    }
    float m = sc[0];
#pragma unroll
    for (int j = 1; j < 8; j++) m = fmaxf(m, sc[j]);
    float sum = 0.f;
#pragma unroll
    for (int j = 0; j < 8; j++) { sc[j] = expf(sc[j] - m); sum += sc[j]; }
    float inv = 1.f / sum;
    float* orow = o + ((size_t)b * 8 + i) * 128 + h * 32;
#pragma unroll
    for (int d = 0; d < 32; d++) {
        float a = 0.f;
#pragma unroll
        for (int j = 0; j < 8; j++) a += sc[j] * sv[j * 128 + h * 32 + d];
        orow[d] = a * inv;
    }
}

// ---------------- value head ----------------
__global__ void value_k(const float* __restrict__ comb, const float* __restrict__ Wv,
                        const float* __restrict__ bv, float* __restrict__ out) {
    int t = blockIdx.x * blockDim.x + threadIdx.x;
    if (t >= NTOK) return;
    const float4* cr = (const float4*)(comb + (size_t)t * DIM);
    const float4* wr = (const float4*)Wv;
    float acc = 0.f;
    for (int k = 0; k < DIM / 4; k++) {
        float4 c = cr[k], w = wr[k];
        acc += c.x * w.x + c.y * w.y + c.z * w.z + c.w * w.w;
    }
    out[t] = acc + bv[0];
}

// ---------------- launcher ----------------
extern "C" void kernel_launch(void* const* d_in, const int* in_sizes, int n_in,
                              void* d_out, int out_size) {
    const float* x   = (const float*)d_in[0];
    const float* Wg  = (const float*)d_in[1];
    const float* W1  = (const float*)d_in[2];
    const float* b1  = (const float*)d_in[3];
    const float* W2  = (const float*)d_in[4];
    const float* b2  = (const float*)d_in[5];
    const float* Ws1 = (const float*)d_in[6];
    const float* bs1 = (const float*)d_in[7];
    const float* Ws2 = (const float*)d_in[8];
    const float* bs2 = (const float*)d_in[9];
    const float* rsc = (const float*)d_in[10];
    const float* Wq  = (const float*)d_in[11];
    const float* Wkv = (const float*)d_in[12];
    const float* Wku = (const float*)d_in[13];
    const float* Wvu = (const float*)d_in[14];
    const float* Wao = (const float*)d_in[15];
    const float* Wo  = (const float*)d_in[16];
    const float* bo  = (const float*)d_in[17];
    const float* Wv  = (const float*)d_in[18];
    const float* bv  = (const float*)d_in[19];
    float* outp = (float*)d_out;

    float *hs, *h, *h2, *EO, *comb, *qb, *lat, *kb, *vb, *attn, *ew;
    half *W1T, *W2T, *Ws1T, *Ws2T, *WoT, *WqT, *WkvT, *WkuT, *WvuT, *WaoT;
    int *eidx, *fpos, *counts, *cursor, *rbexp, *ftok;
    cudaGetSymbolAddress((void**)&hs, g_hs);
    cudaGetSymbolAddress((void**)&h, g_h);
    cudaGetSymbolAddress((void**)&h2, g_h2);
    cudaGetSymbolAddress((void**)&EO, g_EO);
    cudaGetSymbolAddress((void**)&comb, g_comb);
    cudaGetSymbolAddress((void**)&qb, g_q);
    cudaGetSymbolAddress((void**)&lat, g_lat);
    cudaGetSymbolAddress((void**)&kb, g_k);
    cudaGetSymbolAddress((void**)&vb, g_v);
    cudaGetSymbolAddress((void**)&attn, g_attn);
    cudaGetSymbolAddress((void**)&ew, g_ew);
    cudaGetSymbolAddress((void**)&W1T, g_W1T);
    cudaGetSymbolAddress((void**)&W2T, g_W2T);
    cudaGetSymbolAddress((void**)&Ws1T, g_Ws1T);
    cudaGetSymbolAddress((void**)&Ws2T, g_Ws2T);
    cudaGetSymbolAddress((void**)&WoT, g_WoT);
    cudaGetSymbolAddress((void**)&WqT, g_WqT);
    cudaGetSymbolAddress((void**)&WkvT, g_WkvT);
    cudaGetSymbolAddress((void**)&WkuT, g_WkuT);
    cudaGetSymbolAddress((void**)&WvuT, g_WvuT);
    cudaGetSymbolAddress((void**)&WaoT, g_WaoT);
    cudaGetSymbolAddress((void**)&eidx, g_eidx);
    cudaGetSymbolAddress((void**)&fpos, g_fpos);
    cudaGetSymbolAddress((void**)&counts, g_counts);
    cudaGetSymbolAddress((void**)&cursor, g_cursor);
    cudaGetSymbolAddress((void**)&rbexp, g_rbexp);
    cudaGetSymbolAddress((void**)&ftok, g_ftok);

    dim3 tb(32, 8);
    // launch order puts the shared-FC1 GEMM 6th for the ncu -s 5 -c 1 window
    transpose_h<<<dim3(32, 32, 1), tb>>>(Ws1, Ws1T, DIM, FDIM);
    zero_k<<<1, 32>>>(counts);
    routing_k<<<NTOK / 128, 128>>>(x, Wg, rsc, eidx, ew, counts);
    setup_k<<<1, 256>>>(counts, cursor, rbexp, ftok);
    scatter_k<<<NTOK / 256, 256>>>(eidx, cursor, ftok, fpos);

    tgemm<1, false, false><<<dim3(8, 128), 256>>>(
        x, Ws1T, hs, DIM, FDIM, bs1, nullptr, nullptr, nullptr);

    transpose_h<<<dim3(32, 32, NEXP), tb>>>(W1, W1T, DIM, FDIM);
    transpose_h<<<dim3(32, 32, NEXP), tb>>>(W2, W2T, FDIM, DIM);
    transpose_h<<<dim3(32, 32, 1), tb>>>(Ws2, Ws2T, FDIM, DIM);
    transpose_h<<<dim3(32, 32, 1), tb>>>(Wo, WoT, DIM, 1024);
    transpose_h<<<dim3(4, 32, 1), tb>>>(Wq, WqT, DIM, 128);
    transpose_h<<<dim3(8, 32, 1), tb>>>(Wkv, WkvT, DIM, 256);
    transpose_h<<<dim3(4, 8, 1), tb>>>(Wku, WkuT, 256, 128);
    transpose_h<<<dim3(4, 8, 1), tb>>>(Wvu, WvuT, 256, 128);
    transpose_h<<<dim3(32, 4, 1), tb>>>(Wao, WaoT, 128, 1024);

    // shared branch FC2 -> EO
    tgemm<0, false, false><<<dim3(8, 128), 256>>>(
        hs, Ws2T, EO, FDIM, DIM, bs2, nullptr, nullptr, nullptr);

    // expert branch: grouped GEMMs over 128-aligned segments -> h2 -> combine
    tgemm<1, true, true><<<dim3(8, NRB), 256>>>(
        x, W1T, h, DIM, FDIM, b1, nullptr, ftok, rbexp);
    tgemm<0, false, true><<<dim3(8, NRB), 256>>>(
        h, W2T, h2, FDIM, DIM, b2, nullptr, nullptr, rbexp);
    combine_k<<<NTOK, 256>>>(EO, h2, fpos, ew);

    // attention projections
    tgemm<0, false, false><<<dim3(1, 128), 256>>>(
        EO, WqT, qb, DIM, 128, nullptr, nullptr, nullptr, nullptr);
    tgemm<0, false, false><<<dim3(2, 128), 256>>>(
        EO, WkvT, lat, DIM, 256, nullptr, nullptr, nullptr, nullptr);
    tgemm<0, false, false><<<dim3(1, 128), 256>>>(
        lat, WkuT, kb, 256, 128, nullptr, nullptr, nullptr, nullptr);
    tgemm<0, false, false><<<dim3(1, 128), 256>>>(
        lat, WvuT, vb, 256, 128, nullptr, nullptr, nullptr, nullptr);

    rope_k<<<(NTOK * 32 + 255) / 256, 256>>>(qb);
    attn_k<<<NTOK / 8, 32>>>(qb, kb, vb, attn);

    // comb = EO + attn @ Wao
    tgemm<3, false, false><<<dim3(8, 128), 256>>>(
        attn, WaoT, comb, 128, DIM, nullptr, EO, nullptr, nullptr);

    // output heads
    tgemm<0, false, false><<<dim3(8, 128), 256>>>(
        comb, WoT, outp, DIM, 1024, bo, nullptr, nullptr, nullptr);
    value_k<<<NTOK / 256, 256>>>(comb, Wv, bv, outp + (size_t)NTOK * 1024);
}